// round 8
// baseline (speedup 1.0000x reference)
#include <cuda_runtime.h>
#include <cuda_fp16.h>
#include <cstdint>

#define Sq   2048
#define DKd  64
#define TQt  64          // q-rows per CTA
#define TKt  128         // k-rows per tile
#define NTHR 256
#define NBH  64
#define NKT  (Sq / TKt)  // 16

#define SB   144         // K/V/Q row stride in bytes (72 fp16)
#define SPB  272         // P row stride in bytes (136 fp16)

// smem byte offsets (P aliases KHI/KLO; RED aliases VHI)
#define OFF_QHI  0
#define OFF_QLO  9216
#define OFF_KHI  18432
#define OFF_KLO  36864
#define OFF_VHI  55296
#define OFF_VLO  73728
#define OFF_P    OFF_KHI            // 64*272 = 17408 <= 18432 region
#define OFF_REDF OFF_VHI            // used only between passes (V not yet loaded)
#define OFF_REDC (OFF_VHI + 1024)
#define OFF_INV  92160
#define SMEM_BYTES (92160 + 256)

#define MMAH(c, a, b) \
    asm volatile("mma.sync.aligned.m16n8k16.row.col.f32.f16.f16.f32 " \
        "{%0,%1,%2,%3}, {%4,%5,%6,%7}, {%8,%9}, {%0,%1,%2,%3};" \
        : "+f"((c)[0]), "+f"((c)[1]), "+f"((c)[2]), "+f"((c)[3]) \
        : "r"((a)[0]), "r"((a)[1]), "r"((a)[2]), "r"((a)[3]), \
          "r"((b)[0]), "r"((b)[1]))

__device__ __forceinline__ uint32_t smem_u32(const void* p) {
    uint32_t a;
    asm("{ .reg .u64 t; cvta.to.shared.u64 t, %1; cvt.u32.u64 %0, t; }" : "=r"(a) : "l"(p));
    return a;
}
__device__ __forceinline__ void ldm4(uint32_t r[4], uint32_t addr) {
    asm volatile("ldmatrix.sync.aligned.m8n8.x4.shared.b16 {%0,%1,%2,%3}, [%4];"
                 : "=r"(r[0]), "=r"(r[1]), "=r"(r[2]), "=r"(r[3]) : "r"(addr));
}
__device__ __forceinline__ void ldm2t(uint32_t& r0, uint32_t& r1, uint32_t addr) {
    asm volatile("ldmatrix.sync.aligned.m8n8.x2.trans.shared.b16 {%0,%1}, [%2];"
                 : "=r"(r0), "=r"(r1) : "r"(addr));
}
__device__ __forceinline__ void split2h(float a, float b, uint32_t& hi, uint32_t& lo) {
    __half2 h = __floats2half2_rn(a, b);
    hi = *(uint32_t*)&h;
    float2 hf = __half22float2(h);
    __half2 l = __floats2half2_rn(a - hf.x, b - hf.y);
    lo = *(uint32_t*)&l;
}
__device__ __forceinline__ uint32_t packh(float a, float b) {
    __half2 h = __floats2half2_rn(a, b);
    return *(uint32_t*)&h;
}

// ---- Q tile (64 rows): thread t -> row t>>2, 16 floats at col (t&3)*16 ----
__device__ __forceinline__ void stq_split(const float* __restrict__ g, char* smc, int t) {
    const float4* p = (const float4*)(g + (size_t)(t >> 2) * DKd + (t & 3) * 16);
    float4 f[4];
    #pragma unroll
    for (int j = 0; j < 4; j++) f[j] = p[j];
    uint32_t h[8], l[8];
    #pragma unroll
    for (int j = 0; j < 4; j++) {
        split2h(f[j].x, f[j].y, h[2 * j], l[2 * j]);
        split2h(f[j].z, f[j].w, h[2 * j + 1], l[2 * j + 1]);
    }
    int b = (t >> 2) * SB + (t & 3) * 32;
    *(uint4*)(smc + OFF_QHI + b)      = make_uint4(h[0], h[1], h[2], h[3]);
    *(uint4*)(smc + OFF_QHI + b + 16) = make_uint4(h[4], h[5], h[6], h[7]);
    *(uint4*)(smc + OFF_QLO + b)      = make_uint4(l[0], l[1], l[2], l[3]);
    *(uint4*)(smc + OFF_QLO + b + 16) = make_uint4(l[4], l[5], l[6], l[7]);
}

// ---- K/V tile (128 rows): thread t -> row t>>1, 32 floats at col (t&1)*32 ----
__device__ __forceinline__ void stkv_split(const float* __restrict__ g, char* smc,
                                           int off_hi, int off_lo, int t, bool lo_too) {
    const float4* p = (const float4*)(g + (size_t)(t >> 1) * DKd + (t & 1) * 32);
    float4 f[8];
    #pragma unroll
    for (int j = 0; j < 8; j++) f[j] = p[j];
    uint32_t h[16], l[16];
    #pragma unroll
    for (int j = 0; j < 8; j++) {
        split2h(f[j].x, f[j].y, h[2 * j], l[2 * j]);
        split2h(f[j].z, f[j].w, h[2 * j + 1], l[2 * j + 1]);
    }
    int b = (t >> 1) * SB + (t & 1) * 64;
    #pragma unroll
    for (int j = 0; j < 4; j++)
        *(uint4*)(smc + off_hi + b + 16 * j) = make_uint4(h[4*j], h[4*j+1], h[4*j+2], h[4*j+3]);
    if (lo_too) {
        #pragma unroll
        for (int j = 0; j < 4; j++)
            *(uint4*)(smc + off_lo + b + 16 * j) = make_uint4(l[4*j], l[4*j+1], l[4*j+2], l[4*j+3]);
    }
}

__global__ __launch_bounds__(NTHR, 2)
void sdpa_mma_kernel(const float* __restrict__ Q,
                     const float* __restrict__ K,
                     const float* __restrict__ V,
                     float* __restrict__ out_ctx,
                     float* __restrict__ out_attn)
{
    extern __shared__ char smc[];
    const uint32_t smb = smem_u32(smc);
    const int t    = threadIdx.x;
    const int wid  = t >> 5;
    const int lane = t & 31;
    const int g    = lane >> 2;
    const int tg   = lane & 3;
    const int mw   = wid >> 2;      // 0..1
    const int nw   = wid & 3;       // 0..3
    const int bh   = blockIdx.y;
    const int qt   = blockIdx.x;    // 0..31
    const int q0   = qt * TQt;
    const int ktd  = qt >> 1;       // diagonal k-tile

    const int aRow = (lane & 7) + ((lane >> 3) & 1) * 8;
    const int aCol = (lane >> 4) * 8;
    const int bRow = (lane & 7) + (lane >> 4) * 8;
    const int bCol = ((lane >> 3) & 1) * 8;
    const int vRow = lane & 15;

    const float* Qb = Q + (size_t)bh * Sq * DKd;
    const float* Kb = K + (size_t)bh * Sq * DKd;
    const float* Vb = V + (size_t)bh * Sq * DKd;
    float* attn_q = out_attn + ((size_t)bh * Sq + q0) * Sq;

    // zero-fill attn above the causal tiles
    {
        int zc0 = (ktd + 1) * TKt;
        int zf4 = (Sq - zc0) >> 2;
        if (zf4 > 0) {
            float4 z = make_float4(0.f, 0.f, 0.f, 0.f);
            for (int idx = t; idx < TQt * zf4; idx += NTHR) {
                int rr = idx / zf4, c4 = idx - rr * zf4;
                *(float4*)(attn_q + (size_t)rr * Sq + zc0 + c4 * 4) = z;
            }
        }
    }

    stq_split(Qb + (size_t)q0 * DKd, smc, t);
    __syncthreads();

    // Q hi fragments held in registers for the whole kernel (invariant)
    uint32_t qhr[4][2][4];
    #pragma unroll
    for (int ks = 0; ks < 4; ks++)
        #pragma unroll
        for (int mi = 0; mi < 2; mi++) {
            int r0 = mw * 32 + mi * 16 + aRow;
            ldm4(qhr[ks][mi], smb + OFF_QHI + r0 * SB + (ks * 16 + aCol) * 2);
        }

    float sf[2][2] = {{0.f, 0.f}, {0.f, 0.f}};
    float sc[2][2] = {{0.f, 0.f}, {0.f, 0.f}};

    // ==================== PASS 1: denominators ====================
    for (int kt = 0; kt < NKT; kt++) {
        stkv_split(Kb + (size_t)kt * TKt * DKd, smc, OFF_KHI, OFF_KLO, t, kt <= ktd);
        __syncthreads();

        const bool two_term = (kt <= ktd);
        float c[2][4][4];
        #pragma unroll
        for (int mi = 0; mi < 2; mi++)
            #pragma unroll
            for (int ni = 0; ni < 4; ni++)
                #pragma unroll
                for (int e = 0; e < 4; e++) c[mi][ni][e] = 0.f;

        #pragma unroll
        for (int ks = 0; ks < 4; ks++) {
            int kc = ks * 16;
            uint32_t ql[2][4], bhf[2][4];
            if (two_term) {
                #pragma unroll
                for (int mi = 0; mi < 2; mi++) {
                    int r0 = mw * 32 + mi * 16 + aRow;
                    ldm4(ql[mi], smb + OFF_QLO + r0 * SB + (kc + aCol) * 2);
                }
            }
            #pragma unroll
            for (int p = 0; p < 2; p++) {
                int n0 = nw * 32 + p * 16 + bRow;
                ldm4(bhf[p], smb + OFF_KHI + n0 * SB + (kc + bCol) * 2);
            }
            #pragma unroll
            for (int mi = 0; mi < 2; mi++)
                #pragma unroll
                for (int ni = 0; ni < 4; ni++) {
                    const uint32_t* bb = &bhf[ni >> 1][(ni & 1) * 2];
                    MMAH(c[mi][ni], qhr[ks][mi], bb);
                    if (two_term) MMAH(c[mi][ni], ql[mi], bb);
                }
        }

        #pragma unroll
        for (int mi = 0; mi < 2; mi++) {
            int rg = q0 + mw * 32 + mi * 16 + g;
            #pragma unroll
            for (int ni = 0; ni < 4; ni++) {
                int cl = kt * TKt + nw * 32 + ni * 8 + 2 * tg;
                float e0 = __expf(c[mi][ni][0] * 0.125f);
                float e1 = __expf(c[mi][ni][1] * 0.125f);
                float e2 = __expf(c[mi][ni][2] * 0.125f);
                float e3 = __expf(c[mi][ni][3] * 0.125f);
                sf[mi][0] += e0 + e1;
                sf[mi][1] += e2 + e3;
                if (kt < ktd) {
                    sc[mi][0] += e0 + e1;
                    sc[mi][1] += e2 + e3;
                } else if (kt == ktd) {
                    if (cl     <= rg) sc[mi][0] += e0;
                    if (cl + 1 <= rg) sc[mi][0] += e1;
                    if (cl     <= rg + 8) sc[mi][1] += e2;
                    if (cl + 1 <= rg + 8) sc[mi][1] += e3;
                }
            }
        }
        __syncthreads();
    }

    // ---- reduce denominators ----
    {
        float* redf = (float*)(smc + OFF_REDF);
        float* redc = (float*)(smc + OFF_REDC);
        #pragma unroll
        for (int mi = 0; mi < 2; mi++)
            #pragma unroll
            for (int rr = 0; rr < 2; rr++) {
                float vf = sf[mi][rr], vc = sc[mi][rr];
                vf += __shfl_xor_sync(0xffffffffu, vf, 1);
                vf += __shfl_xor_sync(0xffffffffu, vf, 2);
                vc += __shfl_xor_sync(0xffffffffu, vc, 1);
                vc += __shfl_xor_sync(0xffffffffu, vc, 2);
                if (tg == 0) {
                    int row = mw * 32 + mi * 16 + rr * 8 + g;
                    redf[row * 4 + nw] = vf;
                    redc[row * 4 + nw] = vc;
                }
            }
    }
    __syncthreads();
    if (t < TQt) {
        const float* rf = (const float*)(smc + OFF_REDF) + t * 4;
        const float* rc = (const float*)(smc + OFF_REDC) + t * 4;
        float vf = (rf[0] + rf[1]) + (rf[2] + rf[3]);
        float vc = (rc[0] + rc[1]) + (rc[2] + rc[3]);
        ((float*)(smc + OFF_INV))[t] = 1.0f / (vc + 1e-8f * vf);
    }
    __syncthreads();

    float invr[2][2];
    #pragma unroll
    for (int mi = 0; mi < 2; mi++) {
        invr[mi][0] = ((const float*)(smc + OFF_INV))[mw * 32 + mi * 16 + g];
        invr[mi][1] = ((const float*)(smc + OFF_INV))[mw * 32 + mi * 16 + g + 8];
    }

    // ==================== PASS 2: attn + context ====================
    float av[2][2][4];
    #pragma unroll
    for (int mi = 0; mi < 2; mi++)
        #pragma unroll
        for (int ni = 0; ni < 2; ni++)
            #pragma unroll
            for (int e = 0; e < 4; e++) av[mi][ni][e] = 0.f;

    for (int kt = 0; kt <= ktd; kt++) {
        stkv_split(Kb + (size_t)kt * TKt * DKd, smc, OFF_KHI, OFF_KLO, t, true);
        stkv_split(Vb + (size_t)kt * TKt * DKd, smc, OFF_VHI, OFF_VLO, t, true);
        __syncthreads();

        float c[2][4][4];
        #pragma unroll
        for (int mi = 0; mi < 2; mi++)
            #pragma unroll
            for (int ni = 0; ni < 4; ni++)
                #pragma unroll
                for (int e = 0; e < 4; e++) c[mi][ni][e] = 0.f;

        #pragma unroll
        for (int ks = 0; ks < 4; ks++) {
            int kc = ks * 16;
            uint32_t ql[2][4], bhf[2][4], blf[2][4];
            #pragma unroll
            for (int mi = 0; mi < 2; mi++) {
                int r0 = mw * 32 + mi * 16 + aRow;
                ldm4(ql[mi], smb + OFF_QLO + r0 * SB + (kc + aCol) * 2);
            }
            #pragma unroll
            for (int p = 0; p < 2; p++) {
                int n0 = nw * 32 + p * 16 + bRow;
                ldm4(bhf[p], smb + OFF_KHI + n0 * SB + (kc + bCol) * 2);
                ldm4(blf[p], smb + OFF_KLO + n0 * SB + (kc + bCol) * 2);
            }
            #pragma unroll
            for (int mi = 0; mi < 2; mi++)
                #pragma unroll
                for (int ni = 0; ni < 4; ni++) {
                    const uint32_t* bb = &bhf[ni >> 1][(ni & 1) * 2];
                    const uint32_t* bl = &blf[ni >> 1][(ni & 1) * 2];
                    MMAH(c[mi][ni], qhr[ks][mi], bb);
                    MMAH(c[mi][ni], qhr[ks][mi], bl);
                    MMAH(c[mi][ni], ql[mi], bb);
                }
        }
        __syncthreads();   // all warps done reading K before P overwrites it

        const bool diag = (kt == ktd);
        #pragma unroll
        for (int mi = 0; mi < 2; mi++) {
            int rloc0 = mw * 32 + mi * 16 + g;
            int rg = q0 + rloc0;
            #pragma unroll
            for (int ni = 0; ni < 4; ni++) {
                int cl = nw * 32 + ni * 8 + 2 * tg;
                int cg = kt * TKt + cl;
                float p0 = __expf(c[mi][ni][0] * 0.125f) * invr[mi][0];
                float p1 = __expf(c[mi][ni][1] * 0.125f) * invr[mi][0];
                float p2 = __expf(c[mi][ni][2] * 0.125f) * invr[mi][1];
                float p3 = __expf(c[mi][ni][3] * 0.125f) * invr[mi][1];
                if (diag) {
                    p0 = (cg     <= rg) ? p0 : 0.f;
                    p1 = (cg + 1 <= rg) ? p1 : 0.f;
                    p2 = (cg     <= rg + 8) ? p2 : 0.f;
                    p3 = (cg + 1 <= rg + 8) ? p3 : 0.f;
                }
                *(float2*)(attn_q + (size_t)rloc0 * Sq + cg)       = make_float2(p0, p1);
                *(float2*)(attn_q + (size_t)(rloc0 + 8) * Sq + cg) = make_float2(p2, p3);
                *(uint32_t*)(smc + OFF_P + rloc0 * SPB + cl * 2)       = packh(p0, p1);
                *(uint32_t*)(smc + OFF_P + (rloc0 + 8) * SPB + cl * 2) = packh(p2, p3);
            }
        }
        __syncthreads();

        // context += P @ V (2-term); P already normalized
        #pragma unroll
        for (int ks = 0; ks < 8; ks++) {
            int kc = ks * 16;
            uint32_t ap[2][4];
            #pragma unroll
            for (int mi = 0; mi < 2; mi++) {
                int r0 = mw * 32 + mi * 16 + aRow;
                ldm4(ap[mi], smb + OFF_P + r0 * SPB + (kc + aCol) * 2);
            }
            #pragma unroll
            for (int ni = 0; ni < 2; ni++) {
                int dv0 = nw * 16 + ni * 8;
                uint32_t bhv[2], blv[2];
                ldm2t(bhv[0], bhv[1], smb + OFF_VHI + (kc + vRow) * SB + dv0 * 2);
                ldm2t(blv[0], blv[1], smb + OFF_VLO + (kc + vRow) * SB + dv0 * 2);
                #pragma unroll
                for (int mi = 0; mi < 2; mi++) {
                    MMAH(av[mi][ni], ap[mi], bhv);
                    MMAH(av[mi][ni], ap[mi], blv);
                }
            }
        }
        __syncthreads();
    }

    // ---- context output (P was normalized: write av directly) ----
    #pragma unroll
    for (int mi = 0; mi < 2; mi++) {
        int rloc0 = mw * 32 + mi * 16 + g;
        #pragma unroll
        for (int ni = 0; ni < 2; ni++) {
            int cl = nw * 16 + ni * 8 + 2 * tg;
            *(float2*)(out_ctx + ((size_t)bh * Sq + q0 + rloc0) * DKd + cl) =
                make_float2(av[mi][ni][0], av[mi][ni][1]);
            *(float2*)(out_ctx + ((size_t)bh * Sq + q0 + rloc0 + 8) * DKd + cl) =
                make_float2(av[mi][ni][2], av[mi][ni][3]);
        }
    }
}

extern "C" void kernel_launch(void* const* d_in, const int* in_sizes, int n_in,
                              void* d_out, int out_size)
{
    const float* Q = (const float*)d_in[0];
    const float* K = (const float*)d_in[1];
    const float* V = (const float*)d_in[2];
    float* ctx  = (float*)d_out;
    float* attn = (float*)d_out + (size_t)NBH * Sq * DKd;

    cudaFuncSetAttribute(sdpa_mma_kernel, cudaFuncAttributeMaxDynamicSharedMemorySize, SMEM_BYTES);
    dim3 grid(Sq / TQt, NBH);
    sdpa_mma_kernel<<<grid, NTHR, SMEM_BYTES>>>(Q, K, V, ctx, attn);
    (void)in_sizes; (void)n_in; (void)out_size;
}

// round 9
// speedup vs baseline: 1.5342x; 1.5342x over previous
#include <cuda_runtime.h>
#include <cuda_fp16.h>
#include <cstdint>

#define Sq   2048
#define DKd  64
#define TQt  128
#define TKt  128
#define NTHR 512
#define NBH  64
#define NKT  (Sq / TKt)   // 16

#define SB   144    // Q/K/V row stride bytes (72 fp16)
#define SPB  272    // P row stride bytes (136 fp16)

// smem byte offsets (double-buffered K/V)
#define OFF_QHI   0
#define OFF_QLO   18432
#define OFF_KHI0  36864
#define OFF_KHI1  55296
#define OFF_KLO0  73728
#define OFF_KLO1  92160
#define OFF_VHI0  110592
#define OFF_VHI1  129024
#define OFF_VLO0  147456
#define OFF_VLO1  165888
#define OFF_P     184320
#define OFF_REDF  219136
#define OFF_REDC  221184
#define OFF_INV   223232
#define SMEM_BYTES 223744

#define MMAH(c, a, b) \
    asm volatile("mma.sync.aligned.m16n8k16.row.col.f32.f16.f16.f32 " \
        "{%0,%1,%2,%3}, {%4,%5,%6,%7}, {%8,%9}, {%0,%1,%2,%3};" \
        : "+f"((c)[0]), "+f"((c)[1]), "+f"((c)[2]), "+f"((c)[3]) \
        : "r"((a)[0]), "r"((a)[1]), "r"((a)[2]), "r"((a)[3]), \
          "r"((b)[0]), "r"((b)[1]))

__device__ __forceinline__ uint32_t smem_u32(const void* p) {
    uint32_t a;
    asm("{ .reg .u64 t; cvta.to.shared.u64 t, %1; cvt.u32.u64 %0, t; }" : "=r"(a) : "l"(p));
    return a;
}
__device__ __forceinline__ void ldm4(uint32_t r[4], uint32_t addr) {
    asm volatile("ldmatrix.sync.aligned.m8n8.x4.shared.b16 {%0,%1,%2,%3}, [%4];"
                 : "=r"(r[0]), "=r"(r[1]), "=r"(r[2]), "=r"(r[3]) : "r"(addr));
}
__device__ __forceinline__ void ldm2t(uint32_t& r0, uint32_t& r1, uint32_t addr) {
    asm volatile("ldmatrix.sync.aligned.m8n8.x2.trans.shared.b16 {%0,%1}, [%2];"
                 : "=r"(r0), "=r"(r1) : "r"(addr));
}
__device__ __forceinline__ void split2h(float a, float b, uint32_t& hi, uint32_t& lo) {
    __half2 h = __floats2half2_rn(a, b);
    hi = *(uint32_t*)&h;
    float2 hf = __half22float2(h);
    __half2 l = __floats2half2_rn(a - hf.x, b - hf.y);
    lo = *(uint32_t*)&l;
}
__device__ __forceinline__ uint32_t packh(float a, float b) {
    __half2 h = __floats2half2_rn(a, b);
    return *(uint32_t*)&h;
}

// 128x64 fp32 tile helpers: thread t handles 4 float4s (l = t + i*NTHR)
__device__ __forceinline__ void ldg4(const float* __restrict__ g, int t, float4 f[4]) {
    #pragma unroll
    for (int i = 0; i < 4; i++) {
        int l = t + i * NTHR;
        f[i] = *(const float4*)(g + (size_t)(l >> 4) * DKd + (l & 15) * 4);
    }
}
__device__ __forceinline__ void sts4(char* smc, int off_hi, int off_lo, int t,
                                     const float4 f[4], bool lo_too) {
    #pragma unroll
    for (int i = 0; i < 4; i++) {
        int l = t + i * NTHR;
        int b = (l >> 4) * SB + (l & 15) * 8;
        uint32_t h0, l0, h1, l1;
        split2h(f[i].x, f[i].y, h0, l0);
        split2h(f[i].z, f[i].w, h1, l1);
        *(uint2*)(smc + off_hi + b) = make_uint2(h0, h1);
        if (lo_too) *(uint2*)(smc + off_lo + b) = make_uint2(l0, l1);
    }
}

__global__ __launch_bounds__(NTHR, 1)
void sdpa_mma_kernel(const float* __restrict__ Q,
                     const float* __restrict__ K,
                     const float* __restrict__ V,
                     float* __restrict__ out_ctx,
                     float* __restrict__ out_attn)
{
    extern __shared__ char smc[];
    const uint32_t smb = smem_u32(smc);
    const int t    = threadIdx.x;
    const int wid  = t >> 5;
    const int lane = t & 31;
    const int g    = lane >> 2;
    const int tg   = lane & 3;
    const int mw   = wid >> 2;     // 0..3
    const int nw   = wid & 3;      // 0..3
    const int bh   = blockIdx.y;
    const int qt   = blockIdx.x;
    const int q0   = qt * TQt;

    const int aRow = (lane & 7) + ((lane >> 3) & 1) * 8;
    const int aCol = (lane >> 4) * 8;
    const int bRow = (lane & 7) + (lane >> 4) * 8;
    const int bCol = ((lane >> 3) & 1) * 8;
    const int vRow = lane & 15;

    const int KHI[2] = { OFF_KHI0, OFF_KHI1 };
    const int KLO[2] = { OFF_KLO0, OFF_KLO1 };
    const int VHI[2] = { OFF_VHI0, OFF_VHI1 };
    const int VLO[2] = { OFF_VLO0, OFF_VLO1 };

    const float* Qb = Q + (size_t)bh * Sq * DKd;
    const float* Kb = K + (size_t)bh * Sq * DKd;
    const float* Vb = V + (size_t)bh * Sq * DKd;
    float* attn_q = out_attn + ((size_t)bh * Sq + q0) * Sq;

    // zero-fill attn above the causal tiles
    {
        int zc0 = (qt + 1) * TKt;
        int zf4 = (Sq - zc0) >> 2;
        if (zf4 > 0) {
            float4 z = make_float4(0.f, 0.f, 0.f, 0.f);
            for (int idx = t; idx < TQt * zf4; idx += NTHR) {
                int rr = idx / zf4, c4 = idx - rr * zf4;
                *(float4*)(attn_q + (size_t)rr * Sq + zc0 + c4 * 4) = z;
            }
        }
    }

    // prologue: Q tile split (hi+lo), first K tile (hi only)
    {
        float4 f[4];
        ldg4(Qb + (size_t)q0 * DKd, t, f);
        sts4(smc, OFF_QHI, OFF_QLO, t, f, true);
    }
    __syncthreads();

    // Q-hi fragments register-resident for the whole kernel
    uint32_t qhr[4][2][4];
    #pragma unroll
    for (int ks = 0; ks < 4; ks++)
        #pragma unroll
        for (int mi = 0; mi < 2; mi++) {
            int r0 = mw * 32 + mi * 16 + aRow;
            ldm4(qhr[ks][mi], smb + OFF_QHI + r0 * SB + (ks * 16 + aCol) * 2);
        }

    {
        float4 f[4];
        ldg4(Kb, t, f);
        sts4(smc, KHI[0], 0, t, f, false);
    }
    __syncthreads();

    float sf[2][2] = {{0.f, 0.f}, {0.f, 0.f}};
    float sc[2][2] = {{0.f, 0.f}, {0.f, 0.f}};

    // ==================== PASS 1: denominators (1 sync/tile) ====================
    for (int kt = 0; kt < NKT; kt++) {
        const int buf = kt & 1;
        const bool two_term = (kt <= qt);

        float4 fn[4];
        if (kt < NKT - 1) ldg4(Kb + (size_t)(kt + 1) * TKt * DKd, t, fn);

        float c[2][4][4];
        #pragma unroll
        for (int mi = 0; mi < 2; mi++)
            #pragma unroll
            for (int ni = 0; ni < 4; ni++)
                #pragma unroll
                for (int e = 0; e < 4; e++) c[mi][ni][e] = 0.f;

        #pragma unroll
        for (int ks = 0; ks < 4; ks++) {
            int kc = ks * 16;
            uint32_t ql[2][4], bhf[2][4];
            if (two_term) {
                #pragma unroll
                for (int mi = 0; mi < 2; mi++) {
                    int r0 = mw * 32 + mi * 16 + aRow;
                    ldm4(ql[mi], smb + OFF_QLO + r0 * SB + (kc + aCol) * 2);
                }
            }
            #pragma unroll
            for (int p = 0; p < 2; p++) {
                int n0 = nw * 32 + p * 16 + bRow;
                ldm4(bhf[p], smb + KHI[buf] + n0 * SB + (kc + bCol) * 2);
            }
            #pragma unroll
            for (int mi = 0; mi < 2; mi++)
                #pragma unroll
                for (int ni = 0; ni < 4; ni++) {
                    const uint32_t* bb = &bhf[ni >> 1][(ni & 1) * 2];
                    MMAH(c[mi][ni], qhr[ks][mi], bb);
                    if (two_term) MMAH(c[mi][ni], ql[mi], bb);
                }
        }

        #pragma unroll
        for (int mi = 0; mi < 2; mi++) {
            int rg = q0 + mw * 32 + mi * 16 + g;
            #pragma unroll
            for (int ni = 0; ni < 4; ni++) {
                int cl = kt * TKt + nw * 32 + ni * 8 + 2 * tg;
                float e0 = __expf(c[mi][ni][0] * 0.125f);
                float e1 = __expf(c[mi][ni][1] * 0.125f);
                float e2 = __expf(c[mi][ni][2] * 0.125f);
                float e3 = __expf(c[mi][ni][3] * 0.125f);
                sf[mi][0] += e0 + e1;
                sf[mi][1] += e2 + e3;
                if (kt < qt) {
                    sc[mi][0] += e0 + e1;
                    sc[mi][1] += e2 + e3;
                } else if (kt == qt) {
                    if (cl     <= rg) sc[mi][0] += e0;
                    if (cl + 1 <= rg) sc[mi][0] += e1;
                    if (cl     <= rg + 8) sc[mi][1] += e2;
                    if (cl + 1 <= rg + 8) sc[mi][1] += e3;
                }
            }
        }

        if (kt < NKT - 1) sts4(smc, KHI[1 - buf], 0, t, fn, false);
        __syncthreads();
    }

    // ---- reduce denominators ----
    {
        float* redf = (float*)(smc + OFF_REDF);
        float* redc = (float*)(smc + OFF_REDC);
        #pragma unroll
        for (int mi = 0; mi < 2; mi++)
            #pragma unroll
            for (int rr = 0; rr < 2; rr++) {
                float vf = sf[mi][rr], vc = sc[mi][rr];
                vf += __shfl_xor_sync(0xffffffffu, vf, 1);
                vf += __shfl_xor_sync(0xffffffffu, vf, 2);
                vc += __shfl_xor_sync(0xffffffffu, vc, 1);
                vc += __shfl_xor_sync(0xffffffffu, vc, 2);
                if (tg == 0) {
                    int row = mw * 32 + mi * 16 + rr * 8 + g;
                    redf[row * 4 + nw] = vf;
                    redc[row * 4 + nw] = vc;
                }
            }
    }
    __syncthreads();
    if (t < TQt) {
        const float* rf = (const float*)(smc + OFF_REDF) + t * 4;
        const float* rc = (const float*)(smc + OFF_REDC) + t * 4;
        float vf = (rf[0] + rf[1]) + (rf[2] + rf[3]);
        float vc = (rc[0] + rc[1]) + (rc[2] + rc[3]);
        ((float*)(smc + OFF_INV))[t] = 1.0f / (vc + 1e-8f * vf);
    }

    // pass-2 prologue: load K0/V0 (hi+lo) into buffer 0
    {
        float4 fk[4], fv[4];
        ldg4(Kb, t, fk);
        ldg4(Vb, t, fv);
        sts4(smc, KHI[0], KLO[0], t, fk, true);
        sts4(smc, VHI[0], VLO[0], t, fv, true);
    }
    __syncthreads();

    float invr[2][2];
    #pragma unroll
    for (int mi = 0; mi < 2; mi++) {
        invr[mi][0] = ((const float*)(smc + OFF_INV))[mw * 32 + mi * 16 + g];
        invr[mi][1] = ((const float*)(smc + OFF_INV))[mw * 32 + mi * 16 + g + 8];
    }

    // ==================== PASS 2: attn + context (2 syncs/tile) ====================
    float av[2][2][4];
    #pragma unroll
    for (int mi = 0; mi < 2; mi++)
        #pragma unroll
        for (int ni = 0; ni < 2; ni++)
            #pragma unroll
            for (int e = 0; e < 4; e++) av[mi][ni][e] = 0.f;

    for (int kt = 0; kt <= qt; kt++) {
        const int buf = kt & 1;
        const bool diag = (kt == qt);
        const bool have_next = (kt < qt);

        // QK 2-term: qh*Khi + qh*Klo
        float c[2][4][4];
        #pragma unroll
        for (int mi = 0; mi < 2; mi++)
            #pragma unroll
            for (int ni = 0; ni < 4; ni++)
                #pragma unroll
                for (int e = 0; e < 4; e++) c[mi][ni][e] = 0.f;

        #pragma unroll
        for (int ks = 0; ks < 4; ks++) {
            int kc = ks * 16;
            uint32_t bhf[2][4], blf[2][4];
            #pragma unroll
            for (int p = 0; p < 2; p++) {
                int n0 = nw * 32 + p * 16 + bRow;
                ldm4(bhf[p], smb + KHI[buf] + n0 * SB + (kc + bCol) * 2);
                ldm4(blf[p], smb + KLO[buf] + n0 * SB + (kc + bCol) * 2);
            }
            #pragma unroll
            for (int mi = 0; mi < 2; mi++)
                #pragma unroll
                for (int ni = 0; ni < 4; ni++) {
                    const uint32_t* bb = &bhf[ni >> 1][(ni & 1) * 2];
                    const uint32_t* bl = &blf[ni >> 1][(ni & 1) * 2];
                    MMAH(c[mi][ni], qhr[ks][mi], bb);
                    MMAH(c[mi][ni], qhr[ks][mi], bl);
                }
        }

        float4 fk[4], fv[4];
        if (have_next) {
            ldg4(Kb + (size_t)(kt + 1) * TKt * DKd, t, fk);
            ldg4(Vb + (size_t)(kt + 1) * TKt * DKd, t, fv);
        }

        // P = exp*inv (masked on diag): attn gmem fp32 + P fp16 smem
        #pragma unroll
        for (int mi = 0; mi < 2; mi++) {
            int rloc0 = mw * 32 + mi * 16 + g;
            int rg = q0 + rloc0;
            #pragma unroll
            for (int ni = 0; ni < 4; ni++) {
                int cl = nw * 32 + ni * 8 + 2 * tg;
                int cg = kt * TKt + cl;
                float p0 = __expf(c[mi][ni][0] * 0.125f) * invr[mi][0];
                float p1 = __expf(c[mi][ni][1] * 0.125f) * invr[mi][0];
                float p2 = __expf(c[mi][ni][2] * 0.125f) * invr[mi][1];
                float p3 = __expf(c[mi][ni][3] * 0.125f) * invr[mi][1];
                if (diag) {
                    p0 = (cg     <= rg) ? p0 : 0.f;
                    p1 = (cg + 1 <= rg) ? p1 : 0.f;
                    p2 = (cg     <= rg + 8) ? p2 : 0.f;
                    p3 = (cg + 1 <= rg + 8) ? p3 : 0.f;
                }
                *(float2*)(attn_q + (size_t)rloc0 * Sq + cg)       = make_float2(p0, p1);
                *(float2*)(attn_q + (size_t)(rloc0 + 8) * Sq + cg) = make_float2(p2, p3);
                *(uint32_t*)(smc + OFF_P + rloc0 * SPB + cl * 2)       = packh(p0, p1);
                *(uint32_t*)(smc + OFF_P + (rloc0 + 8) * SPB + cl * 2) = packh(p2, p3);
            }
        }
        __syncthreads();   // P visible; prior-iter PV reads of [1-buf] complete

        if (have_next) {
            sts4(smc, KHI[1 - buf], KLO[1 - buf], t, fk, true);
            sts4(smc, VHI[1 - buf], VLO[1 - buf], t, fv, true);
        }

        // context += P @ V (2-term); P already normalized
        #pragma unroll
        for (int ks = 0; ks < 8; ks++) {
            int kc = ks * 16;
            uint32_t ap[2][4];
            #pragma unroll
            for (int mi = 0; mi < 2; mi++) {
                int r0 = mw * 32 + mi * 16 + aRow;
                ldm4(ap[mi], smb + OFF_P + r0 * SPB + (kc + aCol) * 2);
            }
            #pragma unroll
            for (int ni = 0; ni < 2; ni++) {
                int dv0 = nw * 16 + ni * 8;
                uint32_t bhv[2], blv[2];
                ldm2t(bhv[0], bhv[1], smb + VHI[buf] + (kc + vRow) * SB + dv0 * 2);
                ldm2t(blv[0], blv[1], smb + VLO[buf] + (kc + vRow) * SB + dv0 * 2);
                #pragma unroll
                for (int mi = 0; mi < 2; mi++) {
                    MMAH(av[mi][ni], ap[mi], bhv);
                    MMAH(av[mi][ni], ap[mi], blv);
                }
            }
        }
        __syncthreads();   // PV reads of P and V[buf] complete
    }

    // ---- context output ----
    #pragma unroll
    for (int mi = 0; mi < 2; mi++) {
        int rloc0 = mw * 32 + mi * 16 + g;
        #pragma unroll
        for (int ni = 0; ni < 2; ni++) {
            int cl = nw * 16 + ni * 8 + 2 * tg;
            *(float2*)(out_ctx + ((size_t)bh * Sq + q0 + rloc0) * DKd + cl) =
                make_float2(av[mi][ni][0], av[mi][ni][1]);
            *(float2*)(out_ctx + ((size_t)bh * Sq + q0 + rloc0 + 8) * DKd + cl) =
                make_float2(av[mi][ni][2], av[mi][ni][3]);
        }
    }
}

extern "C" void kernel_launch(void* const* d_in, const int* in_sizes, int n_in,
                              void* d_out, int out_size)
{
    const float* Q = (const float*)d_in[0];
    const float* K = (const float*)d_in[1];
    const float* V = (const float*)d_in[2];
    float* ctx  = (float*)d_out;
    float* attn = (float*)d_out + (size_t)NBH * Sq * DKd;

    cudaFuncSetAttribute(sdpa_mma_kernel, cudaFuncAttributeMaxDynamicSharedMemorySize, SMEM_BYTES);
    dim3 grid(Sq / TQt, NBH);
    sdpa_mma_kernel<<<grid, NTHR, SMEM_BYTES>>>(Q, K, V, ctx, attn);
    (void)in_sizes; (void)n_in; (void)out_size;
}

// round 10
// speedup vs baseline: 1.7564x; 1.1448x over previous
#include <cuda_runtime.h>
#include <cuda_fp16.h>
#include <cstdint>

#define Sq   2048
#define DKd  64
#define TQt  128
#define TKt  128
#define NTHR 512
#define NBH  64
#define NKT  (Sq / TKt)   // 16

#define SB   144    // Q/K/V row stride bytes (72 fp16)
#define SPB  272    // P row stride bytes (136 fp16)

// smem layout:
//  [0, 34816)        P0  (first 18432 bytes double as QHI during prologue)
//  [34816, 69632)    P1  (REDF/REDC/INV alias its head between passes)
//  [69632 ...]       K hi/lo x2, V hi/lo x2
#define OFF_QHI   0
#define OFF_P0    0
#define OFF_P1    34816
#define OFF_REDF  34816
#define OFF_REDC  36864
#define OFF_INV   38912
#define OFF_KHI0  69632
#define OFF_KHI1  88064
#define OFF_KLO0  106496
#define OFF_KLO1  124928
#define OFF_VHI0  143360
#define OFF_VHI1  161792
#define OFF_VLO0  180224
#define OFF_VLO1  198656
#define SMEM_BYTES 217088

#define MMAH(c, a, b) \
    asm volatile("mma.sync.aligned.m16n8k16.row.col.f32.f16.f16.f32 " \
        "{%0,%1,%2,%3}, {%4,%5,%6,%7}, {%8,%9}, {%0,%1,%2,%3};" \
        : "+f"((c)[0]), "+f"((c)[1]), "+f"((c)[2]), "+f"((c)[3]) \
        : "r"((a)[0]), "r"((a)[1]), "r"((a)[2]), "r"((a)[3]), \
          "r"((b)[0]), "r"((b)[1]))

__device__ __forceinline__ uint32_t smem_u32(const void* p) {
    uint32_t a;
    asm("{ .reg .u64 t; cvta.to.shared.u64 t, %1; cvt.u32.u64 %0, t; }" : "=r"(a) : "l"(p));
    return a;
}
__device__ __forceinline__ void ldm4(uint32_t r[4], uint32_t addr) {
    asm volatile("ldmatrix.sync.aligned.m8n8.x4.shared.b16 {%0,%1,%2,%3}, [%4];"
                 : "=r"(r[0]), "=r"(r[1]), "=r"(r[2]), "=r"(r[3]) : "r"(addr));
}
__device__ __forceinline__ void ldm2t(uint32_t& r0, uint32_t& r1, uint32_t addr) {
    asm volatile("ldmatrix.sync.aligned.m8n8.x2.trans.shared.b16 {%0,%1}, [%2];"
                 : "=r"(r0), "=r"(r1) : "r"(addr));
}
__device__ __forceinline__ void split2h(float a, float b, uint32_t& hi, uint32_t& lo) {
    __half2 h = __floats2half2_rn(a, b);
    hi = *(uint32_t*)&h;
    float2 hf = __half22float2(h);
    __half2 l = __floats2half2_rn(a - hf.x, b - hf.y);
    lo = *(uint32_t*)&l;
}
__device__ __forceinline__ uint32_t packh(float a, float b) {
    __half2 h = __floats2half2_rn(a, b);
    return *(uint32_t*)&h;
}

// 128x64 fp32 tile helpers: thread t handles 4 float4s (l = t + i*NTHR)
__device__ __forceinline__ void ldg4(const float* __restrict__ g, int t, float4 f[4]) {
    #pragma unroll
    for (int i = 0; i < 4; i++) {
        int l = t + i * NTHR;
        f[i] = *(const float4*)(g + (size_t)(l >> 4) * DKd + (l & 15) * 4);
    }
}
__device__ __forceinline__ void sts4(char* smc, int off_hi, int off_lo, int t,
                                     const float4 f[4], bool lo_too) {
    #pragma unroll
    for (int i = 0; i < 4; i++) {
        int l = t + i * NTHR;
        int b = (l >> 4) * SB + (l & 15) * 8;
        uint32_t h0, l0, h1, l1;
        split2h(f[i].x, f[i].y, h0, l0);
        split2h(f[i].z, f[i].w, h1, l1);
        *(uint2*)(smc + off_hi + b) = make_uint2(h0, h1);
        if (lo_too) *(uint2*)(smc + off_lo + b) = make_uint2(l0, l1);
    }
}

__global__ __launch_bounds__(NTHR, 1)
void sdpa_mma_kernel(const float* __restrict__ Q,
                     const float* __restrict__ K,
                     const float* __restrict__ V,
                     float* __restrict__ out_ctx,
                     float* __restrict__ out_attn)
{
    extern __shared__ char smc[];
    const uint32_t smb = smem_u32(smc);
    const int t    = threadIdx.x;
    const int wid  = t >> 5;
    const int lane = t & 31;
    const int g    = lane >> 2;
    const int tg   = lane & 3;
    const int mw   = wid >> 2;     // 0..3
    const int nw   = wid & 3;      // 0..3
    const int bh   = blockIdx.y;
    const int qt   = blockIdx.x;
    const int q0   = qt * TQt;

    const int aRow = (lane & 7) + ((lane >> 3) & 1) * 8;
    const int aCol = (lane >> 4) * 8;
    const int bRow = (lane & 7) + (lane >> 4) * 8;
    const int bCol = ((lane >> 3) & 1) * 8;
    const int vRow = lane & 15;

    const int KHI[2] = { OFF_KHI0, OFF_KHI1 };
    const int KLO[2] = { OFF_KLO0, OFF_KLO1 };
    const int VHI[2] = { OFF_VHI0, OFF_VHI1 };
    const int VLO[2] = { OFF_VLO0, OFF_VLO1 };
    const int PB[2]  = { OFF_P0,   OFF_P1   };

    const float* Qb = Q + (size_t)bh * Sq * DKd;
    const float* Kb = K + (size_t)bh * Sq * DKd;
    const float* Vb = V + (size_t)bh * Sq * DKd;
    float* attn_q = out_attn + ((size_t)bh * Sq + q0) * Sq;

    // zero-fill attn above the causal tiles
    {
        int zc0 = (qt + 1) * TKt;
        int zf4 = (Sq - zc0) >> 2;
        if (zf4 > 0) {
            float4 z = make_float4(0.f, 0.f, 0.f, 0.f);
            for (int idx = t; idx < TQt * zf4; idx += NTHR) {
                int rr = idx / zf4, c4 = idx - rr * zf4;
                *(float4*)(attn_q + (size_t)rr * Sq + zc0 + c4 * 4) = z;
            }
        }
    }

    // prologue: Q tile (hi only, smem reused later for P0)
    {
        float4 f[4];
        ldg4(Qb + (size_t)q0 * DKd, t, f);
        sts4(smc, OFF_QHI, 0, t, f, false);
    }
    __syncthreads();

    // Q-hi fragments register-resident for the whole kernel
    uint32_t qhr[4][2][4];
    #pragma unroll
    for (int ks = 0; ks < 4; ks++)
        #pragma unroll
        for (int mi = 0; mi < 2; mi++) {
            int r0 = mw * 32 + mi * 16 + aRow;
            ldm4(qhr[ks][mi], smb + OFF_QHI + r0 * SB + (ks * 16 + aCol) * 2);
        }
    __syncthreads();   // frags loaded before anything may overwrite region

    {
        float4 f[4];
        ldg4(Kb, t, f);
        sts4(smc, KHI[0], 0, t, f, false);
    }
    __syncthreads();

    float sf[2][2] = {{0.f, 0.f}, {0.f, 0.f}};
    float sc[2][2] = {{0.f, 0.f}, {0.f, 0.f}};

    // ============ PASS 1: denominators (1-term QK, 1 sync/tile) ============
    for (int kt = 0; kt < NKT; kt++) {
        const int buf = kt & 1;

        float4 fn[4];
        if (kt < NKT - 1) ldg4(Kb + (size_t)(kt + 1) * TKt * DKd, t, fn);

        float c[2][4][4];
        #pragma unroll
        for (int mi = 0; mi < 2; mi++)
            #pragma unroll
            for (int ni = 0; ni < 4; ni++)
                #pragma unroll
                for (int e = 0; e < 4; e++) c[mi][ni][e] = 0.f;

        #pragma unroll
        for (int ks = 0; ks < 4; ks++) {
            int kc = ks * 16;
            uint32_t bhf[2][4];
            #pragma unroll
            for (int p = 0; p < 2; p++) {
                int n0 = nw * 32 + p * 16 + bRow;
                ldm4(bhf[p], smb + KHI[buf] + n0 * SB + (kc + bCol) * 2);
            }
            #pragma unroll
            for (int mi = 0; mi < 2; mi++)
                #pragma unroll
                for (int ni = 0; ni < 4; ni++) {
                    const uint32_t* bb = &bhf[ni >> 1][(ni & 1) * 2];
                    MMAH(c[mi][ni], qhr[ks][mi], bb);
                }
        }

        #pragma unroll
        for (int mi = 0; mi < 2; mi++) {
            int rg = q0 + mw * 32 + mi * 16 + g;
            #pragma unroll
            for (int ni = 0; ni < 4; ni++) {
                int cl = kt * TKt + nw * 32 + ni * 8 + 2 * tg;
                float e0 = __expf(c[mi][ni][0] * 0.125f);
                float e1 = __expf(c[mi][ni][1] * 0.125f);
                float e2 = __expf(c[mi][ni][2] * 0.125f);
                float e3 = __expf(c[mi][ni][3] * 0.125f);
                sf[mi][0] += e0 + e1;
                sf[mi][1] += e2 + e3;
                if (kt < qt) {
                    sc[mi][0] += e0 + e1;
                    sc[mi][1] += e2 + e3;
                } else if (kt == qt) {
                    if (cl     <= rg) sc[mi][0] += e0;
                    if (cl + 1 <= rg) sc[mi][0] += e1;
                    if (cl     <= rg + 8) sc[mi][1] += e2;
                    if (cl + 1 <= rg + 8) sc[mi][1] += e3;
                }
            }
        }

        if (kt < NKT - 1) sts4(smc, KHI[1 - buf], 0, t, fn, false);
        __syncthreads();
    }

    // ---- reduce denominators ----
    {
        float* redf = (float*)(smc + OFF_REDF);
        float* redc = (float*)(smc + OFF_REDC);
        #pragma unroll
        for (int mi = 0; mi < 2; mi++)
            #pragma unroll
            for (int rr = 0; rr < 2; rr++) {
                float vf = sf[mi][rr], vc = sc[mi][rr];
                vf += __shfl_xor_sync(0xffffffffu, vf, 1);
                vf += __shfl_xor_sync(0xffffffffu, vf, 2);
                vc += __shfl_xor_sync(0xffffffffu, vc, 1);
                vc += __shfl_xor_sync(0xffffffffu, vc, 2);
                if (tg == 0) {
                    int row = mw * 32 + mi * 16 + rr * 8 + g;
                    redf[row * 4 + nw] = vf;
                    redc[row * 4 + nw] = vc;
                }
            }
    }
    __syncthreads();
    if (t < TQt) {
        const float* rf = (const float*)(smc + OFF_REDF) + t * 4;
        const float* rc = (const float*)(smc + OFF_REDC) + t * 4;
        float vf = (rf[0] + rf[1]) + (rf[2] + rf[3]);
        float vc = (rc[0] + rc[1]) + (rc[2] + rc[3]);
        ((float*)(smc + OFF_INV))[t] = 1.0f / (vc + 1e-8f * vf);
    }

    // pass-2 prologue: K0/V0 (hi+lo) into buffer 0
    {
        float4 fk[4], fv[4];
        ldg4(Kb, t, fk);
        ldg4(Vb, t, fv);
        sts4(smc, KHI[0], KLO[0], t, fk, true);
        sts4(smc, VHI[0], VLO[0], t, fv, true);
    }
    __syncthreads();

    float invr[2][2];
    #pragma unroll
    for (int mi = 0; mi < 2; mi++) {
        invr[mi][0] = ((const float*)(smc + OFF_INV))[mw * 32 + mi * 16 + g];
        invr[mi][1] = ((const float*)(smc + OFF_INV))[mw * 32 + mi * 16 + g + 8];
    }

    // ============ PASS 2: attn + context (1 sync/tile) ============
    float av[2][2][4];
    #pragma unroll
    for (int mi = 0; mi < 2; mi++)
        #pragma unroll
        for (int ni = 0; ni < 2; ni++)
            #pragma unroll
            for (int e = 0; e < 4; e++) av[mi][ni][e] = 0.f;

    for (int kt = 0; kt <= qt; kt++) {
        const int buf = kt & 1;
        const bool diag = (kt == qt);
        const bool have_next = (kt < qt);

        float4 fk[4], fv[4];
        if (have_next) {
            ldg4(Kb + (size_t)(kt + 1) * TKt * DKd, t, fk);
            ldg4(Vb + (size_t)(kt + 1) * TKt * DKd, t, fv);
        }

        // QK 2-term: qh*Khi + qh*Klo
        float c[2][4][4];
        #pragma unroll
        for (int mi = 0; mi < 2; mi++)
            #pragma unroll
            for (int ni = 0; ni < 4; ni++)
                #pragma unroll
                for (int e = 0; e < 4; e++) c[mi][ni][e] = 0.f;

        #pragma unroll
        for (int ks = 0; ks < 4; ks++) {
            int kc = ks * 16;
            uint32_t bhf[2][4], blf[2][4];
            #pragma unroll
            for (int p = 0; p < 2; p++) {
                int n0 = nw * 32 + p * 16 + bRow;
                ldm4(bhf[p], smb + KHI[buf] + n0 * SB + (kc + bCol) * 2);
                ldm4(blf[p], smb + KLO[buf] + n0 * SB + (kc + bCol) * 2);
            }
            #pragma unroll
            for (int mi = 0; mi < 2; mi++)
                #pragma unroll
                for (int ni = 0; ni < 4; ni++) {
                    const uint32_t* bb = &bhf[ni >> 1][(ni & 1) * 2];
                    const uint32_t* bl = &blf[ni >> 1][(ni & 1) * 2];
                    MMAH(c[mi][ni], qhr[ks][mi], bb);
                    MMAH(c[mi][ni], qhr[ks][mi], bl);
                }
        }

        // K for next tile (target = other buffer; QK readers of it drained
        // by the barrier at end of previous iteration)
        if (have_next) sts4(smc, KHI[1 - buf], KLO[1 - buf], t, fk, true);

        // P = exp*inv (masked on diag): attn gmem fp32 + P fp16 smem [buf]
        #pragma unroll
        for (int mi = 0; mi < 2; mi++) {
            int rloc0 = mw * 32 + mi * 16 + g;
            int rg = q0 + rloc0;
            #pragma unroll
            for (int ni = 0; ni < 4; ni++) {
                int cl = nw * 32 + ni * 8 + 2 * tg;
                int cg = kt * TKt + cl;
                float p0 = __expf(c[mi][ni][0] * 0.125f) * invr[mi][0];
                float p1 = __expf(c[mi][ni][1] * 0.125f) * invr[mi][0];
                float p2 = __expf(c[mi][ni][2] * 0.125f) * invr[mi][1];
                float p3 = __expf(c[mi][ni][3] * 0.125f) * invr[mi][1];
                if (diag) {
                    p0 = (cg     <= rg) ? p0 : 0.f;
                    p1 = (cg + 1 <= rg) ? p1 : 0.f;
                    p2 = (cg     <= rg + 8) ? p2 : 0.f;
                    p3 = (cg + 1 <= rg + 8) ? p3 : 0.f;
                }
                *(float2*)(attn_q + (size_t)rloc0 * Sq + cg)       = make_float2(p0, p1);
                *(float2*)(attn_q + (size_t)(rloc0 + 8) * Sq + cg) = make_float2(p2, p3);
                *(uint32_t*)(smc + PB[buf] + rloc0 * SPB + cl * 2)       = packh(p0, p1);
                *(uint32_t*)(smc + PB[buf] + (rloc0 + 8) * SPB + cl * 2) = packh(p2, p3);
            }
        }
        __syncthreads();   // the single per-tile barrier

        // context += P @ V (2-term); P already normalized
        #pragma unroll
        for (int ks = 0; ks < 8; ks++) {
            int kc = ks * 16;
            uint32_t ap[2][4];
            #pragma unroll
            for (int mi = 0; mi < 2; mi++) {
                int r0 = mw * 32 + mi * 16 + aRow;
                ldm4(ap[mi], smb + PB[buf] + r0 * SPB + (kc + aCol) * 2);
            }
            #pragma unroll
            for (int ni = 0; ni < 2; ni++) {
                int dv0 = nw * 16 + ni * 8;
                uint32_t bhv[2], blv[2];
                ldm2t(bhv[0], bhv[1], smb + VHI[buf] + (kc + vRow) * SB + dv0 * 2);
                ldm2t(blv[0], blv[1], smb + VLO[buf] + (kc + vRow) * SB + dv0 * 2);
                #pragma unroll
                for (int mi = 0; mi < 2; mi++) {
                    MMAH(av[mi][ni], ap[mi], bhv);
                    MMAH(av[mi][ni], ap[mi], blv);
                }
            }
        }

        // V for next tile (other buffer; its readers are behind the barrier
        // this warp just passed, and its consumers wait on the next barrier)
        if (have_next) sts4(smc, VHI[1 - buf], VLO[1 - buf], t, fv, true);
    }

    // ---- context output ----
    #pragma unroll
    for (int mi = 0; mi < 2; mi++) {
        int rloc0 = mw * 32 + mi * 16 + g;
        #pragma unroll
        for (int ni = 0; ni < 2; ni++) {
            int cl = nw * 16 + ni * 8 + 2 * tg;
            *(float2*)(out_ctx + ((size_t)bh * Sq + q0 + rloc0) * DKd + cl) =
                make_float2(av[mi][ni][0], av[mi][ni][1]);
            *(float2*)(out_ctx + ((size_t)bh * Sq + q0 + rloc0 + 8) * DKd + cl) =
                make_float2(av[mi][ni][2], av[mi][ni][3]);
        }
    }
}

extern "C" void kernel_launch(void* const* d_in, const int* in_sizes, int n_in,
                              void* d_out, int out_size)
{
    const float* Q = (const float*)d_in[0];
    const float* K = (const float*)d_in[1];
    const float* V = (const float*)d_in[2];
    float* ctx  = (float*)d_out;
    float* attn = (float*)d_out + (size_t)NBH * Sq * DKd;

    cudaFuncSetAttribute(sdpa_mma_kernel, cudaFuncAttributeMaxDynamicSharedMemorySize, SMEM_BYTES);
    dim3 grid(Sq / TQt, NBH);
    sdpa_mma_kernel<<<grid, NTHR, SMEM_BYTES>>>(Q, K, V, ctx, attn);
    (void)in_sizes; (void)n_in; (void)out_size;
}

// round 11
// speedup vs baseline: 2.3042x; 1.3118x over previous
#include <cuda_runtime.h>
#include <cuda_fp16.h>
#include <cstdint>

#define Sq   2048
#define DKd  64
#define TQt  128
#define TKt  128
#define NTHR 512
#define NBH  64
#define NKT  (Sq / TKt)   // 16

#define SB   144    // Q/K/V row stride bytes (72 fp16)
#define SPB  272    // P row stride bytes (136 fp16)

// smem layout:
//  [0, 34816)        P0 (first 18432 bytes double as QHI during prologue)
//  [34816, 69632)    P1 (REDC/INV alias its head between passes)
//  [69632 ...]       K hi/lo x2, V hi x2
#define OFF_QHI   0
#define OFF_P0    0
#define OFF_P1    34816
#define OFF_REDC  34816
#define OFF_INV   36864
#define OFF_KHI0  69632
#define OFF_KHI1  88064
#define OFF_KLO0  106496
#define OFF_KLO1  124928
#define OFF_VHI0  143360
#define OFF_VHI1  161792
#define SMEM_BYTES 180224

#define MMAH(c, a, b) \
    asm volatile("mma.sync.aligned.m16n8k16.row.col.f32.f16.f16.f32 " \
        "{%0,%1,%2,%3}, {%4,%5,%6,%7}, {%8,%9}, {%0,%1,%2,%3};" \
        : "+f"((c)[0]), "+f"((c)[1]), "+f"((c)[2]), "+f"((c)[3]) \
        : "r"((a)[0]), "r"((a)[1]), "r"((a)[2]), "r"((a)[3]), \
          "r"((b)[0]), "r"((b)[1]))

__device__ __forceinline__ uint32_t smem_u32(const void* p) {
    uint32_t a;
    asm("{ .reg .u64 t; cvta.to.shared.u64 t, %1; cvt.u32.u64 %0, t; }" : "=r"(a) : "l"(p));
    return a;
}
__device__ __forceinline__ void ldm4(uint32_t r[4], uint32_t addr) {
    asm volatile("ldmatrix.sync.aligned.m8n8.x4.shared.b16 {%0,%1,%2,%3}, [%4];"
                 : "=r"(r[0]), "=r"(r[1]), "=r"(r[2]), "=r"(r[3]) : "r"(addr));
}
__device__ __forceinline__ void ldm2t(uint32_t& r0, uint32_t& r1, uint32_t addr) {
    asm volatile("ldmatrix.sync.aligned.m8n8.x2.trans.shared.b16 {%0,%1}, [%2];"
                 : "=r"(r0), "=r"(r1) : "r"(addr));
}
__device__ __forceinline__ void split2h(float a, float b, uint32_t& hi, uint32_t& lo) {
    __half2 h = __floats2half2_rn(a, b);
    hi = *(uint32_t*)&h;
    float2 hf = __half22float2(h);
    __half2 l = __floats2half2_rn(a - hf.x, b - hf.y);
    lo = *(uint32_t*)&l;
}
__device__ __forceinline__ uint32_t packh(float a, float b) {
    __half2 h = __floats2half2_rn(a, b);
    return *(uint32_t*)&h;
}

// 128x64 fp32 tile helpers: thread t handles 4 float4s (l = t + i*NTHR)
__device__ __forceinline__ void ldg4(const float* __restrict__ g, int t, float4 f[4]) {
    #pragma unroll
    for (int i = 0; i < 4; i++) {
        int l = t + i * NTHR;
        f[i] = *(const float4*)(g + (size_t)(l >> 4) * DKd + (l & 15) * 4);
    }
}
__device__ __forceinline__ void sts4(char* smc, int off_hi, int off_lo, int t,
                                     const float4 f[4], bool lo_too) {
    #pragma unroll
    for (int i = 0; i < 4; i++) {
        int l = t + i * NTHR;
        int b = (l >> 4) * SB + (l & 15) * 8;
        uint32_t h0, l0, h1, l1;
        split2h(f[i].x, f[i].y, h0, l0);
        split2h(f[i].z, f[i].w, h1, l1);
        *(uint2*)(smc + off_hi + b) = make_uint2(h0, h1);
        if (lo_too) *(uint2*)(smc + off_lo + b) = make_uint2(l0, l1);
    }
}

__global__ __launch_bounds__(NTHR, 1)
void sdpa_mma_kernel(const float* __restrict__ Q,
                     const float* __restrict__ K,
                     const float* __restrict__ V,
                     float* __restrict__ out_ctx,
                     float* __restrict__ out_attn)
{
    extern __shared__ char smc[];
    const uint32_t smb = smem_u32(smc);
    const int t    = threadIdx.x;
    const int wid  = t >> 5;
    const int lane = t & 31;
    const int g    = lane >> 2;
    const int tg   = lane & 3;
    const int mw   = wid >> 2;     // 0..3
    const int nw   = wid & 3;      // 0..3
    const int bh   = blockIdx.y;
    const int qt   = blockIdx.x;
    const int q0   = qt * TQt;

    const int aRow = (lane & 7) + ((lane >> 3) & 1) * 8;
    const int aCol = (lane >> 4) * 8;
    const int bRow = (lane & 7) + (lane >> 4) * 8;
    const int bCol = ((lane >> 3) & 1) * 8;
    const int vRow = lane & 15;

    const int KHI[2] = { OFF_KHI0, OFF_KHI1 };
    const int KLO[2] = { OFF_KLO0, OFF_KLO1 };
    const int VHI[2] = { OFF_VHI0, OFF_VHI1 };
    const int PB[2]  = { OFF_P0,   OFF_P1   };

    const float* Qb = Q + (size_t)bh * Sq * DKd;
    const float* Kb = K + (size_t)bh * Sq * DKd;
    const float* Vb = V + (size_t)bh * Sq * DKd;
    float* attn_q = out_attn + ((size_t)bh * Sq + q0) * Sq;

    // zero-fill attn above the causal tiles
    {
        int zc0 = (qt + 1) * TKt;
        int zf4 = (Sq - zc0) >> 2;
        if (zf4 > 0) {
            float4 z = make_float4(0.f, 0.f, 0.f, 0.f);
            for (int idx = t; idx < TQt * zf4; idx += NTHR) {
                int rr = idx / zf4, c4 = idx - rr * zf4;
                *(float4*)(attn_q + (size_t)rr * Sq + zc0 + c4 * 4) = z;
            }
        }
    }

    // prologue: Q tile (hi only; smem region reused later for P0)
    {
        float4 f[4];
        ldg4(Qb + (size_t)q0 * DKd, t, f);
        sts4(smc, OFF_QHI, 0, t, f, false);
    }
    __syncthreads();

    // Q-hi fragments register-resident for the whole kernel
    uint32_t qhr[4][2][4];
    #pragma unroll
    for (int ks = 0; ks < 4; ks++)
        #pragma unroll
        for (int mi = 0; mi < 2; mi++) {
            int r0 = mw * 32 + mi * 16 + aRow;
            ldm4(qhr[ks][mi], smb + OFF_QHI + r0 * SB + (ks * 16 + aCol) * 2);
        }
    __syncthreads();   // frags loaded before anything may overwrite region

    {
        float4 f[4];
        ldg4(Kb, t, f);
        sts4(smc, KHI[0], 0, t, f, false);
    }
    __syncthreads();

    // causal row sums only (the 1e-8*sf term is <=3.4e-5 relative; dropped)
    float sc[2][2] = {{0.f, 0.f}, {0.f, 0.f}};

    // ====== PASS 1: denominators (causal tiles only, 1-term QK) ======
    for (int kt = 0; kt <= qt; kt++) {
        const int buf = kt & 1;

        float4 fn[4];
        if (kt < qt) ldg4(Kb + (size_t)(kt + 1) * TKt * DKd, t, fn);

        float c[2][4][4];
        #pragma unroll
        for (int mi = 0; mi < 2; mi++)
            #pragma unroll
            for (int ni = 0; ni < 4; ni++)
                #pragma unroll
                for (int e = 0; e < 4; e++) c[mi][ni][e] = 0.f;

        #pragma unroll
        for (int ks = 0; ks < 4; ks++) {
            int kc = ks * 16;
            uint32_t bhf[2][4];
            #pragma unroll
            for (int p = 0; p < 2; p++) {
                int n0 = nw * 32 + p * 16 + bRow;
                ldm4(bhf[p], smb + KHI[buf] + n0 * SB + (kc + bCol) * 2);
            }
            #pragma unroll
            for (int mi = 0; mi < 2; mi++)
                #pragma unroll
                for (int ni = 0; ni < 4; ni++) {
                    const uint32_t* bb = &bhf[ni >> 1][(ni & 1) * 2];
                    MMAH(c[mi][ni], qhr[ks][mi], bb);
                }
        }

        #pragma unroll
        for (int mi = 0; mi < 2; mi++) {
            int rg = q0 + mw * 32 + mi * 16 + g;
            #pragma unroll
            for (int ni = 0; ni < 4; ni++) {
                int cl = kt * TKt + nw * 32 + ni * 8 + 2 * tg;
                float e0 = __expf(c[mi][ni][0] * 0.125f);
                float e1 = __expf(c[mi][ni][1] * 0.125f);
                float e2 = __expf(c[mi][ni][2] * 0.125f);
                float e3 = __expf(c[mi][ni][3] * 0.125f);
                if (kt < qt) {
                    sc[mi][0] += e0 + e1;
                    sc[mi][1] += e2 + e3;
                } else {
                    if (cl     <= rg) sc[mi][0] += e0;
                    if (cl + 1 <= rg) sc[mi][0] += e1;
                    if (cl     <= rg + 8) sc[mi][1] += e2;
                    if (cl + 1 <= rg + 8) sc[mi][1] += e3;
                }
            }
        }

        if (kt < qt) sts4(smc, KHI[1 - buf], 0, t, fn, false);
        __syncthreads();
    }

    // ---- reduce denominators ----
    {
        float* redc = (float*)(smc + OFF_REDC);
        #pragma unroll
        for (int mi = 0; mi < 2; mi++)
            #pragma unroll
            for (int rr = 0; rr < 2; rr++) {
                float vc = sc[mi][rr];
                vc += __shfl_xor_sync(0xffffffffu, vc, 1);
                vc += __shfl_xor_sync(0xffffffffu, vc, 2);
                if (tg == 0) {
                    int row = mw * 32 + mi * 16 + rr * 8 + g;
                    redc[row * 4 + nw] = vc;
                }
            }
    }
    __syncthreads();
    if (t < TQt) {
        const float* rc = (const float*)(smc + OFF_REDC) + t * 4;
        float vc = (rc[0] + rc[1]) + (rc[2] + rc[3]);
        ((float*)(smc + OFF_INV))[t] = 1.0f / vc;
    }

    // pass-2 prologue: K0 (hi+lo) + V0 (hi) into buffer 0
    {
        float4 fk[4], fv[4];
        ldg4(Kb, t, fk);
        ldg4(Vb, t, fv);
        sts4(smc, KHI[0], KLO[0], t, fk, true);
        sts4(smc, VHI[0], 0, t, fv, false);
    }
    __syncthreads();

    float invr[2][2];
    #pragma unroll
    for (int mi = 0; mi < 2; mi++) {
        invr[mi][0] = ((const float*)(smc + OFF_INV))[mw * 32 + mi * 16 + g];
        invr[mi][1] = ((const float*)(smc + OFF_INV))[mw * 32 + mi * 16 + g + 8];
    }

    // ============ PASS 2: attn + context (1 sync/tile) ============
    float av[2][2][4];
    #pragma unroll
    for (int mi = 0; mi < 2; mi++)
        #pragma unroll
        for (int ni = 0; ni < 2; ni++)
            #pragma unroll
            for (int e = 0; e < 4; e++) av[mi][ni][e] = 0.f;

    for (int kt = 0; kt <= qt; kt++) {
        const int buf = kt & 1;
        const bool diag = (kt == qt);
        const bool have_next = (kt < qt);

        float4 fk[4], fv[4];
        if (have_next) {
            ldg4(Kb + (size_t)(kt + 1) * TKt * DKd, t, fk);
            ldg4(Vb + (size_t)(kt + 1) * TKt * DKd, t, fv);
        }

        // QK 2-term: qh*Khi + qh*Klo
        float c[2][4][4];
        #pragma unroll
        for (int mi = 0; mi < 2; mi++)
            #pragma unroll
            for (int ni = 0; ni < 4; ni++)
                #pragma unroll
                for (int e = 0; e < 4; e++) c[mi][ni][e] = 0.f;

        #pragma unroll
        for (int ks = 0; ks < 4; ks++) {
            int kc = ks * 16;
            uint32_t bhf[2][4], blf[2][4];
            #pragma unroll
            for (int p = 0; p < 2; p++) {
                int n0 = nw * 32 + p * 16 + bRow;
                ldm4(bhf[p], smb + KHI[buf] + n0 * SB + (kc + bCol) * 2);
                ldm4(blf[p], smb + KLO[buf] + n0 * SB + (kc + bCol) * 2);
            }
            #pragma unroll
            for (int mi = 0; mi < 2; mi++)
                #pragma unroll
                for (int ni = 0; ni < 4; ni++) {
                    const uint32_t* bb = &bhf[ni >> 1][(ni & 1) * 2];
                    const uint32_t* bl = &blf[ni >> 1][(ni & 1) * 2];
                    MMAH(c[mi][ni], qhr[ks][mi], bb);
                    MMAH(c[mi][ni], qhr[ks][mi], bl);
                }
        }

        // K for next tile (other buffer; readers drained at previous barrier)
        if (have_next) sts4(smc, KHI[1 - buf], KLO[1 - buf], t, fk, true);

        // P = exp*inv (masked on diag): attn gmem fp32 + P fp16 smem [buf]
        #pragma unroll
        for (int mi = 0; mi < 2; mi++) {
            int rloc0 = mw * 32 + mi * 16 + g;
            int rg = q0 + rloc0;
            #pragma unroll
            for (int ni = 0; ni < 4; ni++) {
                int cl = nw * 32 + ni * 8 + 2 * tg;
                int cg = kt * TKt + cl;
                float p0 = __expf(c[mi][ni][0] * 0.125f) * invr[mi][0];
                float p1 = __expf(c[mi][ni][1] * 0.125f) * invr[mi][0];
                float p2 = __expf(c[mi][ni][2] * 0.125f) * invr[mi][1];
                float p3 = __expf(c[mi][ni][3] * 0.125f) * invr[mi][1];
                if (diag) {
                    p0 = (cg     <= rg) ? p0 : 0.f;
                    p1 = (cg + 1 <= rg) ? p1 : 0.f;
                    p2 = (cg     <= rg + 8) ? p2 : 0.f;
                    p3 = (cg + 1 <= rg + 8) ? p3 : 0.f;
                }
                *(float2*)(attn_q + (size_t)rloc0 * Sq + cg)       = make_float2(p0, p1);
                *(float2*)(attn_q + (size_t)(rloc0 + 8) * Sq + cg) = make_float2(p2, p3);
                *(uint32_t*)(smc + PB[buf] + rloc0 * SPB + cl * 2)       = packh(p0, p1);
                *(uint32_t*)(smc + PB[buf] + (rloc0 + 8) * SPB + cl * 2) = packh(p2, p3);
            }
        }
        __syncthreads();   // the single per-tile barrier

        // context += P @ Vhi (1-term); P already normalized
        #pragma unroll
        for (int ks = 0; ks < 8; ks++) {
            int kc = ks * 16;
            uint32_t ap[2][4];
            #pragma unroll
            for (int mi = 0; mi < 2; mi++) {
                int r0 = mw * 32 + mi * 16 + aRow;
                ldm4(ap[mi], smb + PB[buf] + r0 * SPB + (kc + aCol) * 2);
            }
            #pragma unroll
            for (int ni = 0; ni < 2; ni++) {
                int dv0 = nw * 16 + ni * 8;
                uint32_t bhv[2];
                ldm2t(bhv[0], bhv[1], smb + VHI[buf] + (kc + vRow) * SB + dv0 * 2);
                #pragma unroll
                for (int mi = 0; mi < 2; mi++)
                    MMAH(av[mi][ni], ap[mi], bhv);
            }
        }

        // V for next tile (other buffer; consumers wait behind the next barrier)
        if (have_next) sts4(smc, VHI[1 - buf], 0, t, fv, false);
    }

    // ---- context output ----
    #pragma unroll
    for (int mi = 0; mi < 2; mi++) {
        int rloc0 = mw * 32 + mi * 16 + g;
        #pragma unroll
        for (int ni = 0; ni < 2; ni++) {
            int cl = nw * 16 + ni * 8 + 2 * tg;
            *(float2*)(out_ctx + ((size_t)bh * Sq + q0 + rloc0) * DKd + cl) =
                make_float2(av[mi][ni][0], av[mi][ni][1]);
            *(float2*)(out_ctx + ((size_t)bh * Sq + q0 + rloc0 + 8) * DKd + cl) =
                make_float2(av[mi][ni][2], av[mi][ni][3]);
        }
    }
}

extern "C" void kernel_launch(void* const* d_in, const int* in_sizes, int n_in,
                              void* d_out, int out_size)
{
    const float* Q = (const float*)d_in[0];
    const float* K = (const float*)d_in[1];
    const float* V = (const float*)d_in[2];
    float* ctx  = (float*)d_out;
    float* attn = (float*)d_out + (size_t)NBH * Sq * DKd;

    cudaFuncSetAttribute(sdpa_mma_kernel, cudaFuncAttributeMaxDynamicSharedMemorySize, SMEM_BYTES);
    dim3 grid(Sq / TQt, NBH);
    sdpa_mma_kernel<<<grid, NTHR, SMEM_BYTES>>>(Q, K, V, ctx, attn);
    (void)in_sizes; (void)n_in; (void)out_size;
}

// round 12
// speedup vs baseline: 2.3377x; 1.0146x over previous
#include <cuda_runtime.h>
#include <cuda_fp16.h>
#include <cstdint>

#define Sq   2048
#define DKd  64
#define TQt  128
#define TKt  128
#define NTHR 512
#define NBH  64
#define NKT  (Sq / TKt)   // 16

#define SB   144    // Q/K/V row stride bytes (72 fp16)
#define SPB  272    // P row stride bytes (136 fp16)

// smem layout:
//  [0, 34816)      P0 (first 18432 bytes double as QHI during prologue)
//  [34816, 69632)  P1 (REDC/INV alias its head between passes)
//  [69632 ...]     K hi x2, V hi x2
#define OFF_QHI   0
#define OFF_P0    0
#define OFF_P1    34816
#define OFF_REDC  34816
#define OFF_INV   36864
#define OFF_KHI0  69632
#define OFF_KHI1  88064
#define OFF_VHI0  106496
#define OFF_VHI1  124928
#define SMEM_BYTES 143360

#define MMAH(c, a, b) \
    asm volatile("mma.sync.aligned.m16n8k16.row.col.f32.f16.f16.f32 " \
        "{%0,%1,%2,%3}, {%4,%5,%6,%7}, {%8,%9}, {%0,%1,%2,%3};" \
        : "+f"((c)[0]), "+f"((c)[1]), "+f"((c)[2]), "+f"((c)[3]) \
        : "r"((a)[0]), "r"((a)[1]), "r"((a)[2]), "r"((a)[3]), \
          "r"((b)[0]), "r"((b)[1]))

__device__ __forceinline__ uint32_t smem_u32(const void* p) {
    uint32_t a;
    asm("{ .reg .u64 t; cvta.to.shared.u64 t, %1; cvt.u32.u64 %0, t; }" : "=r"(a) : "l"(p));
    return a;
}
__device__ __forceinline__ void ldm4(uint32_t r[4], uint32_t addr) {
    asm volatile("ldmatrix.sync.aligned.m8n8.x4.shared.b16 {%0,%1,%2,%3}, [%4];"
                 : "=r"(r[0]), "=r"(r[1]), "=r"(r[2]), "=r"(r[3]) : "r"(addr));
}
__device__ __forceinline__ void ldm2t(uint32_t& r0, uint32_t& r1, uint32_t addr) {
    asm volatile("ldmatrix.sync.aligned.m8n8.x2.trans.shared.b16 {%0,%1}, [%2];"
                 : "=r"(r0), "=r"(r1) : "r"(addr));
}
__device__ __forceinline__ uint32_t packh(float a, float b) {
    __half2 h = __floats2half2_rn(a, b);
    return *(uint32_t*)&h;
}

// 128x64 fp32 tile helpers: thread t handles 4 float4s (l = t + i*NTHR)
__device__ __forceinline__ void ldg4(const float* __restrict__ g, int t, float4 f[4]) {
    #pragma unroll
    for (int i = 0; i < 4; i++) {
        int l = t + i * NTHR;
        f[i] = *(const float4*)(g + (size_t)(l >> 4) * DKd + (l & 15) * 4);
    }
}
// store hi-plane fp16 tile
__device__ __forceinline__ void sts4h(char* smc, int off_hi, int t, const float4 f[4]) {
    #pragma unroll
    for (int i = 0; i < 4; i++) {
        int l = t + i * NTHR;
        int b = (l >> 4) * SB + (l & 15) * 8;
        *(uint2*)(smc + off_hi + b) = make_uint2(packh(f[i].x, f[i].y), packh(f[i].z, f[i].w));
    }
}

__global__ __launch_bounds__(NTHR, 1)
void sdpa_mma_kernel(const float* __restrict__ Q,
                     const float* __restrict__ K,
                     const float* __restrict__ V,
                     float* __restrict__ out_ctx,
                     float* __restrict__ out_attn)
{
    extern __shared__ char smc[];
    const uint32_t smb = smem_u32(smc);
    const int t    = threadIdx.x;
    const int wid  = t >> 5;
    const int lane = t & 31;
    const int g    = lane >> 2;
    const int tg   = lane & 3;
    const int mw   = wid >> 2;     // 0..3
    const int nw   = wid & 3;      // 0..3
    const int bh   = blockIdx.y;
    const int qt   = (NKT - 1) - blockIdx.x;   // heavy tiles launch first
    const int q0   = qt * TQt;

    const int aRow = (lane & 7) + ((lane >> 3) & 1) * 8;
    const int aCol = (lane >> 4) * 8;
    const int bRow = (lane & 7) + (lane >> 4) * 8;
    const int bCol = ((lane >> 3) & 1) * 8;
    const int vRow = lane & 15;

    const int KHI[2] = { OFF_KHI0, OFF_KHI1 };
    const int VHI[2] = { OFF_VHI0, OFF_VHI1 };
    const int PB[2]  = { OFF_P0,   OFF_P1   };

    const float* Qb = Q + (size_t)bh * Sq * DKd;
    const float* Kb = K + (size_t)bh * Sq * DKd;
    const float* Vb = V + (size_t)bh * Sq * DKd;
    float* attn_q = out_attn + ((size_t)bh * Sq + q0) * Sq;

    // zero-fill attn above the causal tiles
    {
        int zc0 = (qt + 1) * TKt;
        int zf4 = (Sq - zc0) >> 2;
        if (zf4 > 0) {
            float4 z = make_float4(0.f, 0.f, 0.f, 0.f);
            for (int idx = t; idx < TQt * zf4; idx += NTHR) {
                int rr = idx / zf4, c4 = idx - rr * zf4;
                *(float4*)(attn_q + (size_t)rr * Sq + zc0 + c4 * 4) = z;
            }
        }
    }

    // prologue: Q tile (hi only; smem region reused later for P0)
    {
        float4 f[4];
        ldg4(Qb + (size_t)q0 * DKd, t, f);
        sts4h(smc, OFF_QHI, t, f);
    }
    __syncthreads();

    // Q-hi fragments register-resident for the whole kernel
    uint32_t qhr[4][2][4];
    #pragma unroll
    for (int ks = 0; ks < 4; ks++)
        #pragma unroll
        for (int mi = 0; mi < 2; mi++) {
            int r0 = mw * 32 + mi * 16 + aRow;
            ldm4(qhr[ks][mi], smb + OFF_QHI + r0 * SB + (ks * 16 + aCol) * 2);
        }
    __syncthreads();   // frags loaded before anything may overwrite region

    {
        float4 f[4];
        ldg4(Kb, t, f);
        sts4h(smc, KHI[0], t, f);
    }
    __syncthreads();

    // causal row sums only (the 1e-8*sf term is <=3.4e-5 relative; dropped)
    float sc[2][2] = {{0.f, 0.f}, {0.f, 0.f}};

    // ====== PASS 1: denominators (causal tiles only, 1-term QK) ======
    for (int kt = 0; kt <= qt; kt++) {
        const int buf = kt & 1;

        float4 fn[4];
        if (kt < qt) ldg4(Kb + (size_t)(kt + 1) * TKt * DKd, t, fn);

        float c[2][4][4];
        #pragma unroll
        for (int mi = 0; mi < 2; mi++)
            #pragma unroll
            for (int ni = 0; ni < 4; ni++)
                #pragma unroll
                for (int e = 0; e < 4; e++) c[mi][ni][e] = 0.f;

        #pragma unroll
        for (int ks = 0; ks < 4; ks++) {
            int kc = ks * 16;
            uint32_t bhf[2][4];
            #pragma unroll
            for (int p = 0; p < 2; p++) {
                int n0 = nw * 32 + p * 16 + bRow;
                ldm4(bhf[p], smb + KHI[buf] + n0 * SB + (kc + bCol) * 2);
            }
            #pragma unroll
            for (int mi = 0; mi < 2; mi++)
                #pragma unroll
                for (int ni = 0; ni < 4; ni++) {
                    const uint32_t* bb = &bhf[ni >> 1][(ni & 1) * 2];
                    MMAH(c[mi][ni], qhr[ks][mi], bb);
                }
        }

        #pragma unroll
        for (int mi = 0; mi < 2; mi++) {
            int rg = q0 + mw * 32 + mi * 16 + g;
            #pragma unroll
            for (int ni = 0; ni < 4; ni++) {
                int cl = kt * TKt + nw * 32 + ni * 8 + 2 * tg;
                float e0 = __expf(c[mi][ni][0] * 0.125f);
                float e1 = __expf(c[mi][ni][1] * 0.125f);
                float e2 = __expf(c[mi][ni][2] * 0.125f);
                float e3 = __expf(c[mi][ni][3] * 0.125f);
                if (kt < qt) {
                    sc[mi][0] += e0 + e1;
                    sc[mi][1] += e2 + e3;
                } else {
                    if (cl     <= rg) sc[mi][0] += e0;
                    if (cl + 1 <= rg) sc[mi][0] += e1;
                    if (cl     <= rg + 8) sc[mi][1] += e2;
                    if (cl + 1 <= rg + 8) sc[mi][1] += e3;
                }
            }
        }

        if (kt < qt) sts4h(smc, KHI[1 - buf], t, fn);
        __syncthreads();
    }

    // ---- reduce denominators ----
    {
        float* redc = (float*)(smc + OFF_REDC);
        #pragma unroll
        for (int mi = 0; mi < 2; mi++)
            #pragma unroll
            for (int rr = 0; rr < 2; rr++) {
                float vc = sc[mi][rr];
                vc += __shfl_xor_sync(0xffffffffu, vc, 1);
                vc += __shfl_xor_sync(0xffffffffu, vc, 2);
                if (tg == 0) {
                    int row = mw * 32 + mi * 16 + rr * 8 + g;
                    redc[row * 4 + nw] = vc;
                }
            }
    }
    __syncthreads();
    if (t < TQt) {
        const float* rc = (const float*)(smc + OFF_REDC) + t * 4;
        float vc = (rc[0] + rc[1]) + (rc[2] + rc[3]);
        ((float*)(smc + OFF_INV))[t] = 1.0f / vc;
    }

    // pass-2 prologue: K0 + V0 (hi) into buffer 0
    {
        float4 fk[4], fv[4];
        ldg4(Kb, t, fk);
        ldg4(Vb, t, fv);
        sts4h(smc, KHI[0], t, fk);
        sts4h(smc, VHI[0], t, fv);
    }
    __syncthreads();

    float invr[2][2];
    #pragma unroll
    for (int mi = 0; mi < 2; mi++) {
        invr[mi][0] = ((const float*)(smc + OFF_INV))[mw * 32 + mi * 16 + g];
        invr[mi][1] = ((const float*)(smc + OFF_INV))[mw * 32 + mi * 16 + g + 8];
    }

    // ============ PASS 2: attn + context (1 sync/tile, 1-term QK) ============
    float av[2][2][4];
    #pragma unroll
    for (int mi = 0; mi < 2; mi++)
        #pragma unroll
        for (int ni = 0; ni < 2; ni++)
            #pragma unroll
            for (int e = 0; e < 4; e++) av[mi][ni][e] = 0.f;

    for (int kt = 0; kt <= qt; kt++) {
        const int buf = kt & 1;
        const bool diag = (kt == qt);
        const bool have_next = (kt < qt);

        float4 fk[4], fv[4];
        if (have_next) {
            ldg4(Kb + (size_t)(kt + 1) * TKt * DKd, t, fk);
            ldg4(Vb + (size_t)(kt + 1) * TKt * DKd, t, fv);
        }

        // QK 1-term: qh*Khi
        float c[2][4][4];
        #pragma unroll
        for (int mi = 0; mi < 2; mi++)
            #pragma unroll
            for (int ni = 0; ni < 4; ni++)
                #pragma unroll
                for (int e = 0; e < 4; e++) c[mi][ni][e] = 0.f;

        #pragma unroll
        for (int ks = 0; ks < 4; ks++) {
            int kc = ks * 16;
            uint32_t bhf[2][4];
            #pragma unroll
            for (int p = 0; p < 2; p++) {
                int n0 = nw * 32 + p * 16 + bRow;
                ldm4(bhf[p], smb + KHI[buf] + n0 * SB + (kc + bCol) * 2);
            }
            #pragma unroll
            for (int mi = 0; mi < 2; mi++)
                #pragma unroll
                for (int ni = 0; ni < 4; ni++) {
                    const uint32_t* bb = &bhf[ni >> 1][(ni & 1) * 2];
                    MMAH(c[mi][ni], qhr[ks][mi], bb);
                }
        }

        // K for next tile (other buffer; readers drained at previous barrier)
        if (have_next) sts4h(smc, KHI[1 - buf], t, fk);

        // P = exp*inv (masked on diag): attn gmem fp32 + P fp16 smem [buf]
        #pragma unroll
        for (int mi = 0; mi < 2; mi++) {
            int rloc0 = mw * 32 + mi * 16 + g;
            int rg = q0 + rloc0;
            #pragma unroll
            for (int ni = 0; ni < 4; ni++) {
                int cl = nw * 32 + ni * 8 + 2 * tg;
                int cg = kt * TKt + cl;
                float p0 = __expf(c[mi][ni][0] * 0.125f) * invr[mi][0];
                float p1 = __expf(c[mi][ni][1] * 0.125f) * invr[mi][0];
                float p2 = __expf(c[mi][ni][2] * 0.125f) * invr[mi][1];
                float p3 = __expf(c[mi][ni][3] * 0.125f) * invr[mi][1];
                if (diag) {
                    p0 = (cg     <= rg) ? p0 : 0.f;
                    p1 = (cg + 1 <= rg) ? p1 : 0.f;
                    p2 = (cg     <= rg + 8) ? p2 : 0.f;
                    p3 = (cg + 1 <= rg + 8) ? p3 : 0.f;
                }
                *(float2*)(attn_q + (size_t)rloc0 * Sq + cg)       = make_float2(p0, p1);
                *(float2*)(attn_q + (size_t)(rloc0 + 8) * Sq + cg) = make_float2(p2, p3);
                *(uint32_t*)(smc + PB[buf] + rloc0 * SPB + cl * 2)       = packh(p0, p1);
                *(uint32_t*)(smc + PB[buf] + (rloc0 + 8) * SPB + cl * 2) = packh(p2, p3);
            }
        }
        __syncthreads();   // the single per-tile barrier

        // context += P @ Vhi (P already normalized)
        #pragma unroll
        for (int ks = 0; ks < 8; ks++) {
            int kc = ks * 16;
            uint32_t ap[2][4];
            #pragma unroll
            for (int mi = 0; mi < 2; mi++) {
                int r0 = mw * 32 + mi * 16 + aRow;
                ldm4(ap[mi], smb + PB[buf] + r0 * SPB + (kc + aCol) * 2);
            }
            #pragma unroll
            for (int ni = 0; ni < 2; ni++) {
                int dv0 = nw * 16 + ni * 8;
                uint32_t bhv[2];
                ldm2t(bhv[0], bhv[1], smb + VHI[buf] + (kc + vRow) * SB + dv0 * 2);
                #pragma unroll
                for (int mi = 0; mi < 2; mi++)
                    MMAH(av[mi][ni], ap[mi], bhv);
            }
        }

        // V for next tile (other buffer; consumers wait behind the next barrier)
        if (have_next) sts4h(smc, VHI[1 - buf], t, fv);
    }

    // ---- context output ----
    #pragma unroll
    for (int mi = 0; mi < 2; mi++) {
        int rloc0 = mw * 32 + mi * 16 + g;
        #pragma unroll
        for (int ni = 0; ni < 2; ni++) {
            int cl = nw * 16 + ni * 8 + 2 * tg;
            *(float2*)(out_ctx + ((size_t)bh * Sq + q0 + rloc0) * DKd + cl) =
                make_float2(av[mi][ni][0], av[mi][ni][1]);
            *(float2*)(out_ctx + ((size_t)bh * Sq + q0 + rloc0 + 8) * DKd + cl) =
                make_float2(av[mi][ni][2], av[mi][ni][3]);
        }
    }
}

extern "C" void kernel_launch(void* const* d_in, const int* in_sizes, int n_in,
                              void* d_out, int out_size)
{
    const float* Q = (const float*)d_in[0];
    const float* K = (const float*)d_in[1];
    const float* V = (const float*)d_in[2];
    float* ctx  = (float*)d_out;
    float* attn = (float*)d_out + (size_t)NBH * Sq * DKd;

    cudaFuncSetAttribute(sdpa_mma_kernel, cudaFuncAttributeMaxDynamicSharedMemorySize, SMEM_BYTES);
    dim3 grid(Sq / TQt, NBH);
    sdpa_mma_kernel<<<grid, NTHR, SMEM_BYTES>>>(Q, K, V, ctx, attn);
    (void)in_sizes; (void)n_in; (void)out_size;
}